// round 15
// baseline (speedup 1.0000x reference)
#include <cuda_runtime.h>
#include <cuda_bf16.h>
#include <cstdint>

// Problem constants
constexpr int Bb = 2;
constexpr int Tt = 2048;
constexpr int Dd = 2048;
constexpr int Nh = 16;
constexpr int Hd = 128;
constexpr int Ss = 2048;
constexpr float QSCALE = 0.08838834764831845f; // 1/sqrt(128)

constexpr size_t NBT = (size_t)Bb * Tt * Dd;   // 8.4M elems

// Scratch (device globals — no allocation allowed)
__device__ __nv_bfloat16 g_xh[NBT], g_xl[NBT];            // split query
__device__ __nv_bfloat16 g_wth[(size_t)3 * Dd * Dd], g_wtl[(size_t)3 * Dd * Dd]; // W_{q,k,v}^T split
__device__ __nv_bfloat16 g_woh[(size_t)Dd * Dd], g_wol[(size_t)Dd * Dd];         // W_o split
__device__ __nv_bfloat16 g_qh[NBT], g_ql[NBT];
__device__ __nv_bfloat16 g_kh[NBT], g_kl[NBT];
__device__ float         g_v[NBT];
__device__ __nv_bfloat16 g_vth[NBT], g_vtl[NBT];          // V^T per head, split
__device__ __nv_bfloat16 g_ctxh[NBT], g_ctxl[NBT];
__device__ float g_l[(size_t)Bb * Nh * Tt];               // row sums of exp(logit)

// ===========================================================================
// Helpers
// ===========================================================================
__device__ __forceinline__ uint32_t smem_u32(const void* p) {
    return (uint32_t)__cvta_generic_to_shared(p);
}
__device__ __forceinline__ void ldsm4(uint32_t* r, uint32_t addr) {
    asm volatile("ldmatrix.sync.aligned.m8n8.x4.shared.b16 {%0,%1,%2,%3}, [%4];"
                 : "=r"(r[0]), "=r"(r[1]), "=r"(r[2]), "=r"(r[3]) : "r"(addr));
}
__device__ __forceinline__ void mma_bf16(float* c, const uint32_t* a, const uint32_t* b) {
    asm volatile(
        "mma.sync.aligned.m16n8k16.row.col.f32.bf16.bf16.f32 "
        "{%0,%1,%2,%3}, {%4,%5,%6,%7}, {%8,%9}, {%0,%1,%2,%3};"
        : "+f"(c[0]), "+f"(c[1]), "+f"(c[2]), "+f"(c[3])
        : "r"(a[0]), "r"(a[1]), "r"(a[2]), "r"(a[3]), "r"(b[0]), "r"(b[1]));
}
__device__ __forceinline__ void split2(float x0, float x1, uint32_t& hi, uint32_t& lo) {
    __nv_bfloat162 h2 = __floats2bfloat162_rn(x0, x1);
    float r0 = x0 - __bfloat162float(h2.x);
    float r1 = x1 - __bfloat162float(h2.y);
    __nv_bfloat162 l2 = __floats2bfloat162_rn(r0, r1);
    hi = *reinterpret_cast<uint32_t*>(&h2);
    lo = *reinterpret_cast<uint32_t*>(&l2);
}
__device__ __forceinline__ void cpa16(uint32_t s, const void* g) {
    asm volatile("cp.async.cg.shared.global [%0], [%1], 16;" :: "r"(s), "l"(g) : "memory");
}
__device__ __forceinline__ void cpa_commit() {
    asm volatile("cp.async.commit_group;" ::: "memory");
}
template<int N> __device__ __forceinline__ void cpa_wait() {
    asm volatile("cp.async.wait_group %0;" :: "n"(N) : "memory");
}

// smem tile: 128 rows x 32 bf16 = 64B/row, XOR-swizzled granules (16B):
//   smem_off(row, g) = row*64 + ((g ^ ((row>>1)&3)) << 4)
constexpr int TILE_U32 = 2048;   // 8192 B
constexpr int TILE_B   = 8192;

constexpr int GEMM_SMEM   = 12 * TILE_B; // 98304  : 3 stages x 4 tiles, 2 CTAs/SM
constexpr int LOGITS_SMEM = 14 * TILE_B; // 114688 : Q 8 + K 3 bufs x 2, 2 CTAs/SM
constexpr int PV_SMEM     = 10 * TILE_B; // 81920  : A 2x2 + B 3x2, 2 CTAs/SM

#define MMA_IDX                                                             \
    const int tid = threadIdx.x;                                            \
    const int wid = tid >> 5;                                               \
    const int l = tid & 31;                                                 \
    const int m_off = (wid & 1) * 64;                                       \
    const int n_off = (wid >> 1) * 32;                                      \
    const int lrow = tid >> 3;                                              \
    const int kq = (tid & 7) * 4;                                           \
    const int rowA0 = m_off + (l & 15);                                     \
    const int rowB0 = n_off + (l & 7) + ((l >> 4) << 3);                    \
    const uint32_t aoff = (uint32_t)(rowA0 * 64);                           \
    const uint32_t boff = (uint32_t)(rowB0 * 64);                           \
    const int swa = (rowA0 >> 1) & 3;                                       \
    const int swb = (rowB0 >> 1) & 3;                                       \
    const int ga = (l >> 4);                                                \
    const int gb = (l >> 3) & 1;                                            \
    (void)lrow; (void)kq; (void)m_off; (void)n_off;                         \
    (void)aoff; (void)boff; (void)swa; (void)swb; (void)ga; (void)gb;

// Copy one 128x32 bf16 tile (64B/row) global -> smem with swizzle.
#define CP_TILE(smbase, gbase, stride)                                     \
    {                                                                      \
        const int g_ = tid & 3;                                            \
        const uint32_t co_ = (uint32_t)((g_ ^ ((tid >> 3) & 3)) << 4);     \
        const int r0_ = tid >> 2;                                          \
        cpa16((smbase) + r0_ * 64 + co_,                                   \
              (const char*)(gbase) + (size_t)r0_ * (stride) + g_ * 16);    \
        cpa16((smbase) + (r0_ + 64) * 64 + co_,                            \
              (const char*)(gbase) + (size_t)(r0_ + 64) * (stride) + g_ * 16); \
    }

// Register split-store (pv A-side): row = lrow + j*32 (swizzle j-invariant).
#define SPLIT_STORE(pH, pL, v, j)                                          \
    {                                                                      \
        const int row_ = lrow + (j) * 32;                                  \
        const int su_ = row_ * 16 +                                        \
            ((((kq >> 3) ^ ((lrow >> 1) & 3))) << 2) + ((kq >> 2) & 1) * 2;\
        uint32_t h0, h1, l0, l1;                                           \
        split2((v).x, (v).y, h0, l0);                                      \
        split2((v).z, (v).w, h1, l1);                                      \
        *reinterpret_cast<uint2*>(&(pH)[su_]) = make_uint2(h0, h1);        \
        *reinterpret_cast<uint2*>(&(pL)[su_]) = make_uint2(l0, l1);        \
    }

#define MMA_CHUNK(acc, BAH, BAL, BBH, BBL)                                 \
    _Pragma("unroll")                                                      \
    for (int ks = 0; ks < 2; ks++) {                                       \
        uint32_t Ah[4][4], Al[4][4], Bh[2][4], Bl[2][4];                   \
        const uint32_t asw = (uint32_t)(((ga + 2 * ks) ^ swa) << 4);       \
        const uint32_t bsw = (uint32_t)(((gb + 2 * ks) ^ swb) << 4);       \
        _Pragma("unroll")                                                  \
        for (int mt = 0; mt < 4; mt++) {                                   \
            const uint32_t ao = aoff + mt * 1024 + asw;                    \
            ldsm4(Ah[mt], (BAH) + ao);                                     \
            ldsm4(Al[mt], (BAL) + ao);                                     \
        }                                                                  \
        _Pragma("unroll")                                                  \
        for (int np = 0; np < 2; np++) {                                   \
            const uint32_t bo = boff + np * 1024 + bsw;                    \
            ldsm4(Bh[np], (BBH) + bo);                                     \
            ldsm4(Bl[np], (BBL) + bo);                                     \
        }                                                                  \
        _Pragma("unroll")                                                  \
        for (int mt = 0; mt < 4; mt++)                                     \
            _Pragma("unroll")                                              \
            for (int nt = 0; nt < 4; nt++) {                               \
                const uint32_t* bh = &Bh[nt >> 1][(nt & 1) * 2];           \
                const uint32_t* bl = &Bl[nt >> 1][(nt & 1) * 2];           \
                mma_bf16(acc[mt][nt], Ah[mt], bh);                         \
                mma_bf16(acc[mt][nt], Ah[mt], bl);                         \
                mma_bf16(acc[mt][nt], Al[mt], bh);                         \
            }                                                              \
    }

#define ACC_ZERO(acc)                                                     \
    _Pragma("unroll")                                                     \
    for (int mt = 0; mt < 4; mt++)                                        \
        _Pragma("unroll")                                                 \
        for (int nt = 0; nt < 4; nt++)                                    \
            _Pragma("unroll")                                             \
            for (int q = 0; q < 4; q++) acc[mt][nt][q] = 0.f;

// ===========================================================================
// Core all-bf16 GEMM, 3-stage cp.async pipeline (depth 2), 2 CTAs/SM.
// ===========================================================================
__device__ __forceinline__ void gemm_core(const __nv_bfloat16* Ah_, const __nv_bfloat16* Al_,
                                          const __nv_bfloat16* Bh_, const __nv_bfloat16* Bl_,
                                          const float* __restrict__ bias, float scale,
                                          float* outF, uint32_t* outH, uint32_t* outL,
                                          int mode, int m0, int n0)
{
    extern __shared__ uint32_t dsm[];
    MMA_IDX
    const uint32_t base = smem_u32(dsm);

    const char* gAh = (const char*)(Ah_ + (size_t)m0 * Dd);
    const char* gAl = (const char*)(Al_ + (size_t)m0 * Dd);
    const char* gBh = (const char*)(Bh_ + (size_t)n0 * Dd);
    const char* gBl = (const char*)(Bl_ + (size_t)n0 * Dd);
    const int WS = Dd * 2;

    float acc[4][4][4];
    ACC_ZERO(acc)

    // prologue: stages 0, 1 (groups 0, 1)
#pragma unroll
    for (int s = 0; s < 2; s++) {
        const uint32_t sb = base + s * 4 * TILE_B;
        CP_TILE(sb + 0 * TILE_B, gAh + s * 64, WS)
        CP_TILE(sb + 1 * TILE_B, gAl + s * 64, WS)
        CP_TILE(sb + 2 * TILE_B, gBh + s * 64, WS)
        CP_TILE(sb + 3 * TILE_B, gBl + s * 64, WS)
        cpa_commit();
    }

#pragma unroll 1
    for (int c = 0; c < 64; c++) {
        cpa_wait<1>();
        __syncthreads();   // stage c%3 ready; MMA of c-1 done -> slot (c+2)%3 free
        if (c + 2 < 64) {
            const uint32_t sb = base + ((c + 2) % 3) * 4 * TILE_B;
            CP_TILE(sb + 0 * TILE_B, gAh + (c + 2) * 64, WS)
            CP_TILE(sb + 1 * TILE_B, gAl + (c + 2) * 64, WS)
            CP_TILE(sb + 2 * TILE_B, gBh + (c + 2) * 64, WS)
            CP_TILE(sb + 3 * TILE_B, gBl + (c + 2) * 64, WS)
        }
        cpa_commit();
        const uint32_t pb = base + (c % 3) * 4 * TILE_B;
        MMA_CHUNK(acc, pb, pb + TILE_B, pb + 2 * TILE_B, pb + 3 * TILE_B)
    }

    const int g = l >> 2, tg = l & 3;
#pragma unroll
    for (int mt = 0; mt < 4; mt++) {
        const int r0 = m0 + m_off + mt * 16 + g;
#pragma unroll
        for (int nt = 0; nt < 4; nt++) {
            const int col = n0 + n_off + nt * 8 + tg * 2;
            const float b0v = bias[col], b1v = bias[col + 1];
            const float v00 = (acc[mt][nt][0] + b0v) * scale;
            const float v01 = (acc[mt][nt][1] + b1v) * scale;
            const float v10 = (acc[mt][nt][2] + b0v) * scale;
            const float v11 = (acc[mt][nt][3] + b1v) * scale;
            if (mode == 0) {
                *reinterpret_cast<float2*>(outF + (size_t)r0 * Dd + col) = make_float2(v00, v01);
                *reinterpret_cast<float2*>(outF + (size_t)(r0 + 8) * Dd + col) = make_float2(v10, v11);
            } else {
                uint32_t h, lo;
                split2(v00, v01, h, lo);
                outH[((size_t)r0 * Dd + col) >> 1] = h;
                outL[((size_t)r0 * Dd + col) >> 1] = lo;
                split2(v10, v11, h, lo);
                outH[((size_t)(r0 + 8) * Dd + col) >> 1] = h;
                outL[((size_t)(r0 + 8) * Dd + col) >> 1] = lo;
            }
        }
    }
}

__global__ __launch_bounds__(256, 2)
void mma_projqk_kernel(const float* __restrict__ bq, const float* __restrict__ bk)
{
    const int z = blockIdx.z;  // 0=Q, 1=K
    const __nv_bfloat16* Bh = g_wth + (size_t)z * Dd * Dd;
    const __nv_bfloat16* Bl = g_wtl + (size_t)z * Dd * Dd;
    const int m0 = blockIdx.y * 128, n0 = blockIdx.x * 128;
    if (z == 0)
        gemm_core(g_xh, g_xl, Bh, Bl, bq, QSCALE, nullptr,
                  (uint32_t*)g_qh, (uint32_t*)g_ql, 1, m0, n0);
    else
        gemm_core(g_xh, g_xl, Bh, Bl, bk, 1.0f, nullptr,
                  (uint32_t*)g_kh, (uint32_t*)g_kl, 1, m0, n0);
}

__global__ __launch_bounds__(256, 2)
void mma_projv_kernel(const float* __restrict__ bv)
{
    const __nv_bfloat16* Bh = g_wth + (size_t)2 * Dd * Dd;
    const __nv_bfloat16* Bl = g_wtl + (size_t)2 * Dd * Dd;
    gemm_core(g_xh, g_xl, Bh, Bl, bv, 1.0f, g_v, nullptr, nullptr, 0,
              blockIdx.y * 128, blockIdx.x * 128);
}

__global__ __launch_bounds__(256, 2)
void mma_oproj_kernel(const float* __restrict__ ob, float* __restrict__ out)
{
    gemm_core(g_ctxh, g_ctxl, g_woh, g_wol, ob, 1.0f, out, nullptr, nullptr, 0,
              blockIdx.y * 128, blockIdx.x * 128);
}

// ===========================================================================
// Logits: persistent split-Q (tiles 0..7), K streamed depth-2 with 3 buffers
// (tiles 8..13). No max subtraction: stores exp(logit), row sums -> g_l.
// ===========================================================================
__global__ __launch_bounds__(256, 2)
void mma_logits_kernel(const float* __restrict__ biasTS, float* __restrict__ probs)
{
    extern __shared__ uint32_t dsm[];
    __shared__ float red_s[128][4];

    const int bn = blockIdx.y;
    const int b = bn >> 4;
    const int n = bn & 15;
    const int t0 = blockIdx.x * 128;

    const char* gQh = (const char*)(g_qh + (size_t)(b * Tt + t0) * Dd + n * Hd);
    const char* gQl = (const char*)(g_ql + (size_t)(b * Tt + t0) * Dd + n * Hd);
    const char* gKh = (const char*)(g_kh + (size_t)b * Tt * Dd + n * Hd);
    const char* gKl = (const char*)(g_kl + (size_t)b * Tt * Dd + n * Hd);
    float* __restrict__ Lout = probs + (size_t)bn * Tt * Ss;
    const int WS = Dd * 2;

    MMA_IDX
    const uint32_t base = smem_u32(dsm);
    const int g = l >> 2, tg = l & 3;

    // Q persistent + K chunk 0 (group 0); K chunk 1 (group 1).
#pragma unroll
    for (int kc = 0; kc < 4; kc++) {
        CP_TILE(base + (2 * kc) * TILE_B, gQh + kc * 64, WS)
        CP_TILE(base + (2 * kc + 1) * TILE_B, gQl + kc * 64, WS)
    }
    CP_TILE(base + 8 * TILE_B, gKh, WS)
    CP_TILE(base + 9 * TILE_B, gKl, WS)
    cpa_commit();
    CP_TILE(base + 10 * TILE_B, gKh + 64, WS)
    CP_TILE(base + 11 * TILE_B, gKl + 64, WS)
    cpa_commit();

    float srun[4][2];
#pragma unroll
    for (int mt = 0; mt < 4; mt++) { srun[mt][0] = 0.f; srun[mt][1] = 0.f; }

#pragma unroll 1
    for (int st = 0; st < 16; st++) {
        const int s0 = st * 128;
        float acc[4][4][4];
        ACC_ZERO(acc)

#pragma unroll 1
        for (int kc2 = 0; kc2 < 4; kc2++) {
            const int cc = st * 4 + kc2;
            cpa_wait<1>();
            __syncthreads();   // K buf cc%3 ready; MMA of cc-1 done -> slot (cc+2)%3 free
            if (cc + 2 < 64) {
                const int nc = cc + 2;
                const size_t off = (size_t)(nc >> 2) * 128 * WS + (size_t)(nc & 3) * 64;
                const uint32_t sb = base + (8 + (nc % 3) * 2) * TILE_B;
                CP_TILE(sb, gKh + off, WS)
                CP_TILE(sb + TILE_B, gKl + off, WS)
            }
            cpa_commit();
            MMA_CHUNK(acc, base + (2 * kc2) * TILE_B, base + (2 * kc2 + 1) * TILE_B,
                      base + (8 + (cc % 3) * 2) * TILE_B, base + (9 + (cc % 3) * 2) * TILE_B)
        }

        // Epilogue: bias add, exp, store exp-values, accumulate row sums
#pragma unroll
        for (int mt = 0; mt < 4; mt++) {
            const int r1 = t0 + m_off + mt * 16 + g;
            const int r2 = r1 + 8;
            float s1 = 0.f, s2 = 0.f;
#pragma unroll
            for (int nt = 0; nt < 4; nt++) {
                const int col = s0 + n_off + nt * 8 + tg * 2;
                float2 c1 = *reinterpret_cast<const float2*>(biasTS + (size_t)r1 * Ss + col);
                float2 c2 = *reinterpret_cast<const float2*>(biasTS + (size_t)r2 * Ss + col);
                const float e10 = __expf(acc[mt][nt][0] + c1.x);
                const float e11 = __expf(acc[mt][nt][1] + c1.y);
                const float e20 = __expf(acc[mt][nt][2] + c2.x);
                const float e21 = __expf(acc[mt][nt][3] + c2.y);
                s1 += e10 + e11;
                s2 += e20 + e21;
                *reinterpret_cast<float2*>(Lout + (size_t)r1 * Ss + col) = make_float2(e10, e11);
                *reinterpret_cast<float2*>(Lout + (size_t)r2 * Ss + col) = make_float2(e20, e21);
            }
            srun[mt][0] += s1;
            srun[mt][1] += s2;
        }
    }

    // Reduce sums: over 4 lanes (tg) sharing each row, then across 4 n-warps.
#pragma unroll
    for (int mt = 0; mt < 4; mt++)
#pragma unroll
        for (int i = 0; i < 2; i++) {
            float s = srun[mt][i];
            s += __shfl_xor_sync(0xffffffffu, s, 1);
            s += __shfl_xor_sync(0xffffffffu, s, 2);
            if (tg == 0) {
                const int rl = m_off + mt * 16 + g + i * 8;
                red_s[rl][wid >> 1] = s;
            }
        }
    __syncthreads();
    if (tid < 128) {
        g_l[(size_t)bn * Tt + t0 + tid] =
            red_s[tid][0] + red_s[tid][1] + red_s[tid][2] + red_s[tid][3];
    }
}

// ===========================================================================
// Normalize (in-place: probs = exp * inv) + PV -> ctx split bf16.
// A double-buffered (2), B triple-buffered (3) -> ONE barrier per chunk.
// ===========================================================================
__global__ __launch_bounds__(256, 2)
void mma_pv_kernel(float* __restrict__ probs)
{
    extern __shared__ uint32_t dsm[];
    __shared__ float sm_inv[128];

    const int bn = blockIdx.y;
    const int b = bn >> 4;
    const int n = bn & 15;
    const int t0 = blockIdx.x * 128;

    float* __restrict__ Lp = probs + (size_t)bn * Tt * Ss;
    const char* gBh = (const char*)(g_vth + (size_t)bn * Hd * Tt);
    const char* gBl = (const char*)(g_vtl + (size_t)bn * Hd * Tt);
    const int WS = Tt * 2;

    MMA_IDX
    const uint32_t base = smem_u32(dsm);

    if (tid < 128)
        sm_inv[tid] = 1.0f / g_l[(size_t)bn * Tt + t0 + tid];
    __syncthreads();

    const float iv[4] = {sm_inv[lrow], sm_inv[lrow + 32], sm_inv[lrow + 64], sm_inv[lrow + 96]};

    float acc[4][4][4];
    ACC_ZERO(acc)

    // Prologue: A0 (register path), B0 and B1 (cp.async groups 0, 1)
    {
        float4 va[4];
#pragma unroll
        for (int j = 0; j < 4; j++) {
            const int row = lrow + j * 32;
            float4 pv = *reinterpret_cast<const float4*>(Lp + (size_t)(t0 + row) * Ss + kq);
            pv.x *= iv[j]; pv.y *= iv[j]; pv.z *= iv[j]; pv.w *= iv[j];
            *reinterpret_cast<float4*>(Lp + (size_t)(t0 + row) * Ss + kq) = pv;
            va[j] = pv;
        }
#pragma unroll
        for (int j = 0; j < 4; j++) SPLIT_STORE(dsm, dsm + TILE_U32, va[j], j)
        CP_TILE(base + 4 * TILE_B, gBh, WS)
        CP_TILE(base + 5 * TILE_B, gBl, WS)
        cpa_commit();
        CP_TILE(base + 6 * TILE_B, gBh + 64, WS)
        CP_TILE(base + 7 * TILE_B, gBl + 64, WS)
        cpa_commit();
    }

#pragma unroll 1
    for (int c = 0; c < 64; c++) {
        float4 va[4];
        if (c + 1 < 64) {
#pragma unroll
            for (int j = 0; j < 4; j++) {
                const int row = lrow + j * 32;
                va[j] = *reinterpret_cast<const float4*>(
                    Lp + (size_t)(t0 + row) * Ss + (c + 1) * 32 + kq);
            }
        }
        cpa_wait<1>();
        __syncthreads();
        if (c + 1 < 64) {
#pragma unroll
            for (int j = 0; j < 4; j++) {
                const int row = lrow + j * 32;
                va[j].x *= iv[j]; va[j].y *= iv[j];
                va[j].z *= iv[j]; va[j].w *= iv[j];
                *reinterpret_cast<float4*>(
                    Lp + (size_t)(t0 + row) * Ss + (c + 1) * 32 + kq) = va[j];
            }
            uint32_t* ah = dsm + ((c + 1) & 1) * 2 * TILE_U32;
#pragma unroll
            for (int j = 0; j < 4; j++) SPLIT_STORE(ah, ah + TILE_U32, va[j], j)
            if (c + 2 < 64) {
                const uint32_t sb = base + (4 + ((c + 2) % 3) * 2) * TILE_B;
                CP_TILE(sb, gBh + (c + 2) * 64, WS)
                CP_TILE(sb + TILE_B, gBl + (c + 2) * 64, WS)
            }
            cpa_commit();
        }
        const uint32_t ab = base + (c & 1) * 2 * TILE_B;
        const uint32_t bb = base + (4 + (c % 3) * 2) * TILE_B;
        MMA_CHUNK(acc, ab, ab + TILE_B, bb, bb + TILE_B)
    }

    const int g = l >> 2, tg = l & 3;
    uint32_t* ch = (uint32_t*)g_ctxh;
    uint32_t* cl = (uint32_t*)g_ctxl;
#pragma unroll
    for (int mt = 0; mt < 4; mt++) {
        const int r0 = t0 + m_off + mt * 16 + g;
#pragma unroll
        for (int nt = 0; nt < 4; nt++) {
            const int gcol = n * Hd + n_off + nt * 8 + tg * 2;
            uint32_t h, lo;
            split2(acc[mt][nt][0], acc[mt][nt][1], h, lo);
            ch[((size_t)(b * Tt + r0) * Dd + gcol) >> 1] = h;
            cl[((size_t)(b * Tt + r0) * Dd + gcol) >> 1] = lo;
            split2(acc[mt][nt][2], acc[mt][nt][3], h, lo);
            ch[((size_t)(b * Tt + r0 + 8) * Dd + gcol) >> 1] = h;
            cl[((size_t)(b * Tt + r0 + 8) * Dd + gcol) >> 1] = lo;
        }
    }
}

// ===========================================================================
// Prep kernels
// ===========================================================================
__global__ void split_kernel(const float4* __restrict__ src, uint32_t* __restrict__ dh,
                             uint32_t* __restrict__ dl, int n4)
{
    const int i = blockIdx.x * blockDim.x + threadIdx.x;
    if (i < n4) {
        float4 v = src[i];
        uint32_t h0, l0, h1, l1;
        split2(v.x, v.y, h0, l0);
        split2(v.z, v.w, h1, l1);
        dh[i * 2] = h0; dh[i * 2 + 1] = h1;
        dl[i * 2] = l0; dl[i * 2 + 1] = l1;
    }
}

__global__ void transpose_w_split_kernel(const float* __restrict__ Wq,
                                         const float* __restrict__ Wk,
                                         const float* __restrict__ Wv)
{
    __shared__ float ts[32][33];
    const int z = blockIdx.z;
    const float* W = (z == 0) ? Wq : (z == 1) ? Wk : Wv;
    __nv_bfloat16* oh = g_wth + (size_t)z * Dd * Dd;
    __nv_bfloat16* ol = g_wtl + (size_t)z * Dd * Dd;
    const int bx = blockIdx.x * 32, by = blockIdx.y * 32;
    const int tx = threadIdx.x, ty = threadIdx.y;
#pragma unroll
    for (int r = 0; r < 32; r += 8)
        ts[ty + r][tx] = W[(size_t)(by + ty + r) * Dd + bx + tx];
    __syncthreads();
#pragma unroll
    for (int r = 0; r < 32; r += 8) {
        const float v = ts[tx][ty + r];
        const __nv_bfloat16 h = __float2bfloat16(v);
        const __nv_bfloat16 lo = __float2bfloat16(v - __bfloat162float(h));
        const size_t idx = (size_t)(bx + ty + r) * Dd + by + tx;
        oh[idx] = h;
        ol[idx] = lo;
    }
}

// g_vth/g_vtl[bn][h][s] = split(g_v[b][s][n*128+h])
__global__ void transpose_v_split_kernel()
{
    __shared__ float ts[32][33];
    const int bn = blockIdx.z;
    const int b = bn >> 4;
    const int n = bn & 15;
    const int s0 = blockIdx.x * 32, h0 = blockIdx.y * 32;
    const int tx = threadIdx.x, ty = threadIdx.y;
#pragma unroll
    for (int r = 0; r < 32; r += 8)
        ts[ty + r][tx] = g_v[(size_t)(b * Tt + s0 + ty + r) * Dd + n * Hd + h0 + tx];
    __syncthreads();
#pragma unroll
    for (int r = 0; r < 32; r += 8) {
        const float v = ts[tx][ty + r];
        const __nv_bfloat16 h = __float2bfloat16(v);
        const __nv_bfloat16 lo = __float2bfloat16(v - __bfloat162float(h));
        const size_t idx = ((size_t)bn * Hd + h0 + ty + r) * Tt + s0 + tx;
        g_vth[idx] = h;
        g_vtl[idx] = lo;
    }
}

// ===========================================================================
extern "C" void kernel_launch(void* const* d_in, const int* in_sizes, int n_in,
                              void* d_out, int out_size)
{
    const float* query  = (const float*)d_in[0];
    const float* biasTS = (const float*)d_in[1];
    const float* wq = (const float*)d_in[2];
    const float* bq = (const float*)d_in[3];
    const float* wk = (const float*)d_in[4];
    const float* bk = (const float*)d_in[5];
    const float* wv = (const float*)d_in[6];
    const float* bv = (const float*)d_in[7];
    const float* wo = (const float*)d_in[8];
    const float* obias = (const float*)d_in[9];

    float* data_out  = (float*)d_out;
    float* probs_out = data_out + (size_t)Bb * Tt * Dd;

    static bool init_done = false;
    static cudaStream_t s_aux = nullptr;
    static cudaEvent_t ev_fork = nullptr, ev_join = nullptr;
    if (!init_done) {
        cudaFuncSetAttribute(mma_projqk_kernel,
                             cudaFuncAttributeMaxDynamicSharedMemorySize, GEMM_SMEM);
        cudaFuncSetAttribute(mma_projv_kernel,
                             cudaFuncAttributeMaxDynamicSharedMemorySize, GEMM_SMEM);
        cudaFuncSetAttribute(mma_oproj_kernel,
                             cudaFuncAttributeMaxDynamicSharedMemorySize, GEMM_SMEM);
        cudaFuncSetAttribute(mma_logits_kernel,
                             cudaFuncAttributeMaxDynamicSharedMemorySize, LOGITS_SMEM);
        cudaFuncSetAttribute(mma_pv_kernel,
                             cudaFuncAttributeMaxDynamicSharedMemorySize, PV_SMEM);
        cudaStreamCreateWithFlags(&s_aux, cudaStreamNonBlocking);
        cudaEventCreateWithFlags(&ev_fork, cudaEventDisableTiming);
        cudaEventCreateWithFlags(&ev_join, cudaEventDisableTiming);
        init_done = true;
    }

    uint32_t *xh, *xl, *woh, *wol;
    cudaGetSymbolAddress((void**)&xh, g_xh);
    cudaGetSymbolAddress((void**)&xl, g_xl);
    cudaGetSymbolAddress((void**)&woh, g_woh);
    cudaGetSymbolAddress((void**)&wol, g_wol);

    // ---- main stream (0): prep needed by everything ----
    split_kernel<<<(Bb * Tt * Dd / 4 + 255) / 256, 256>>>(
        (const float4*)query, xh, xl, Bb * Tt * Dd / 4);
    transpose_w_split_kernel<<<dim3(Dd / 32, Dd / 32, 3), dim3(32, 8)>>>(wq, wk, wv);

    // ---- fork: aux stream computes the V branch + Wo split ----
    cudaEventRecord(ev_fork, 0);
    cudaStreamWaitEvent(s_aux, ev_fork, 0);
    mma_projv_kernel<<<dim3(Dd / 128, (Bb * Tt) / 128), 256, GEMM_SMEM, s_aux>>>(bv);
    transpose_v_split_kernel<<<dim3(Tt / 32, Hd / 32, Bb * Nh), dim3(32, 8), 0, s_aux>>>();
    split_kernel<<<(Dd * Dd / 4 + 255) / 256, 256, 0, s_aux>>>(
        (const float4*)wo, woh, wol, Dd * Dd / 4);
    cudaEventRecord(ev_join, s_aux);

    // ---- main stream: Q,K branch -> logits (overlaps with V branch) ----
    mma_projqk_kernel<<<dim3(Dd / 128, (Bb * Tt) / 128, 2), 256, GEMM_SMEM>>>(bq, bk);
    mma_logits_kernel<<<dim3(Tt / 128, Bb * Nh), 256, LOGITS_SMEM>>>(biasTS, probs_out);

    // ---- join: pv needs Vt + logits; oproj needs ctx + Wo split ----
    cudaStreamWaitEvent(0, ev_join, 0);
    mma_pv_kernel<<<dim3(Tt / 128, Bb * Nh), 256, PV_SMEM>>>(probs_out);
    mma_oproj_kernel<<<dim3(Dd / 128, (Bb * Tt) / 128), 256, GEMM_SMEM>>>(obias, data_out);
}

// round 16
// speedup vs baseline: 1.0300x; 1.0300x over previous
#include <cuda_runtime.h>
#include <cuda_bf16.h>
#include <cstdint>

// Problem constants
constexpr int Bb = 2;
constexpr int Tt = 2048;
constexpr int Dd = 2048;
constexpr int Nh = 16;
constexpr int Hd = 128;
constexpr int Ss = 2048;
constexpr float QSCALE = 0.08838834764831845f; // 1/sqrt(128)

constexpr size_t NBT = (size_t)Bb * Tt * Dd;   // 8.4M elems

// Scratch (device globals — no allocation allowed)
__device__ __nv_bfloat16 g_xh[NBT], g_xl[NBT];            // split query
__device__ __nv_bfloat16 g_wth[(size_t)3 * Dd * Dd], g_wtl[(size_t)3 * Dd * Dd]; // W_{q,k,v}^T split
__device__ __nv_bfloat16 g_woh[(size_t)Dd * Dd], g_wol[(size_t)Dd * Dd];         // W_o split
__device__ __nv_bfloat16 g_qh[NBT], g_ql[NBT];
__device__ __nv_bfloat16 g_kh[NBT], g_kl[NBT];
__device__ float         g_v[NBT];
__device__ __nv_bfloat16 g_vth[NBT], g_vtl[NBT];          // V^T per head, split
__device__ __nv_bfloat16 g_ctxh[NBT], g_ctxl[NBT];
__device__ float g_l[(size_t)Bb * Nh * Tt];               // row sums of exp(logit)

// ===========================================================================
// Helpers
// ===========================================================================
__device__ __forceinline__ uint32_t smem_u32(const void* p) {
    return (uint32_t)__cvta_generic_to_shared(p);
}
__device__ __forceinline__ void ldsm4(uint32_t* r, uint32_t addr) {
    asm volatile("ldmatrix.sync.aligned.m8n8.x4.shared.b16 {%0,%1,%2,%3}, [%4];"
                 : "=r"(r[0]), "=r"(r[1]), "=r"(r[2]), "=r"(r[3]) : "r"(addr));
}
__device__ __forceinline__ void mma_bf16(float* c, const uint32_t* a, const uint32_t* b) {
    asm volatile(
        "mma.sync.aligned.m16n8k16.row.col.f32.bf16.bf16.f32 "
        "{%0,%1,%2,%3}, {%4,%5,%6,%7}, {%8,%9}, {%0,%1,%2,%3};"
        : "+f"(c[0]), "+f"(c[1]), "+f"(c[2]), "+f"(c[3])
        : "r"(a[0]), "r"(a[1]), "r"(a[2]), "r"(a[3]), "r"(b[0]), "r"(b[1]));
}
__device__ __forceinline__ void split2(float x0, float x1, uint32_t& hi, uint32_t& lo) {
    __nv_bfloat162 h2 = __floats2bfloat162_rn(x0, x1);
    float r0 = x0 - __bfloat162float(h2.x);
    float r1 = x1 - __bfloat162float(h2.y);
    __nv_bfloat162 l2 = __floats2bfloat162_rn(r0, r1);
    hi = *reinterpret_cast<uint32_t*>(&h2);
    lo = *reinterpret_cast<uint32_t*>(&l2);
}
__device__ __forceinline__ void cpa16(uint32_t s, const void* g) {
    asm volatile("cp.async.cg.shared.global [%0], [%1], 16;" :: "r"(s), "l"(g) : "memory");
}
__device__ __forceinline__ void cpa_commit() {
    asm volatile("cp.async.commit_group;" ::: "memory");
}
template<int N> __device__ __forceinline__ void cpa_wait() {
    asm volatile("cp.async.wait_group %0;" :: "n"(N) : "memory");
}

// smem tile: 128 rows x 32 bf16 = 64B/row, XOR-swizzled granules (16B):
//   smem_off(row, g) = row*64 + ((g ^ ((row>>1)&3)) << 4)
constexpr int TILE_U32 = 2048;   // 8192 B
constexpr int TILE_B   = 8192;

constexpr int GEMM_SMEM   = 8  * TILE_B; // 65536  -> 2 CTAs/SM
constexpr int LOGITS_SMEM = 12 * TILE_B; // 98304  -> 2 CTAs/SM
constexpr int PV_SMEM     = 10 * TILE_B; // 81920  -> 2 CTAs/SM

#define MMA_IDX                                                             \
    const int tid = threadIdx.x;                                            \
    const int wid = tid >> 5;                                               \
    const int l = tid & 31;                                                 \
    const int m_off = (wid & 1) * 64;                                       \
    const int n_off = (wid >> 1) * 32;                                      \
    const int lrow = tid >> 3;                                              \
    const int kq = (tid & 7) * 4;                                           \
    const int rowA0 = m_off + (l & 15);                                     \
    const int rowB0 = n_off + (l & 7) + ((l >> 4) << 3);                    \
    const uint32_t aoff = (uint32_t)(rowA0 * 64);                           \
    const uint32_t boff = (uint32_t)(rowB0 * 64);                           \
    const int swa = (rowA0 >> 1) & 3;                                       \
    const int swb = (rowB0 >> 1) & 3;                                       \
    const int ga = (l >> 4);                                                \
    const int gb = (l >> 3) & 1;                                            \
    (void)lrow; (void)kq; (void)m_off; (void)n_off;                         \
    (void)aoff; (void)boff; (void)swa; (void)swb; (void)ga; (void)gb;

// Copy one 128x32 bf16 tile (64B/row) global -> smem with swizzle.
#define CP_TILE(smbase, gbase, stride)                                     \
    {                                                                      \
        const int g_ = tid & 3;                                            \
        const uint32_t co_ = (uint32_t)((g_ ^ ((tid >> 3) & 3)) << 4);     \
        const int r0_ = tid >> 2;                                          \
        cpa16((smbase) + r0_ * 64 + co_,                                   \
              (const char*)(gbase) + (size_t)r0_ * (stride) + g_ * 16);    \
        cpa16((smbase) + (r0_ + 64) * 64 + co_,                            \
              (const char*)(gbase) + (size_t)(r0_ + 64) * (stride) + g_ * 16); \
    }

// Register split-store (pv A-side): row = lrow + j*32 (swizzle j-invariant).
#define SPLIT_STORE(pH, pL, v, j)                                          \
    {                                                                      \
        const int row_ = lrow + (j) * 32;                                  \
        const int su_ = row_ * 16 +                                        \
            ((((kq >> 3) ^ ((lrow >> 1) & 3))) << 2) + ((kq >> 2) & 1) * 2;\
        uint32_t h0, h1, l0, l1;                                           \
        split2((v).x, (v).y, h0, l0);                                      \
        split2((v).z, (v).w, h1, l1);                                      \
        *reinterpret_cast<uint2*>(&(pH)[su_]) = make_uint2(h0, h1);        \
        *reinterpret_cast<uint2*>(&(pL)[su_]) = make_uint2(l0, l1);        \
    }

#define MMA_CHUNK(acc, BAH, BAL, BBH, BBL)                                 \
    _Pragma("unroll")                                                      \
    for (int ks = 0; ks < 2; ks++) {                                       \
        uint32_t Ah[4][4], Al[4][4], Bh[2][4], Bl[2][4];                   \
        const uint32_t asw = (uint32_t)(((ga + 2 * ks) ^ swa) << 4);       \
        const uint32_t bsw = (uint32_t)(((gb + 2 * ks) ^ swb) << 4);       \
        _Pragma("unroll")                                                  \
        for (int mt = 0; mt < 4; mt++) {                                   \
            const uint32_t ao = aoff + mt * 1024 + asw;                    \
            ldsm4(Ah[mt], (BAH) + ao);                                     \
            ldsm4(Al[mt], (BAL) + ao);                                     \
        }                                                                  \
        _Pragma("unroll")                                                  \
        for (int np = 0; np < 2; np++) {                                   \
            const uint32_t bo = boff + np * 1024 + bsw;                    \
            ldsm4(Bh[np], (BBH) + bo);                                     \
            ldsm4(Bl[np], (BBL) + bo);                                     \
        }                                                                  \
        _Pragma("unroll")                                                  \
        for (int mt = 0; mt < 4; mt++)                                     \
            _Pragma("unroll")                                              \
            for (int nt = 0; nt < 4; nt++) {                               \
                const uint32_t* bh = &Bh[nt >> 1][(nt & 1) * 2];           \
                const uint32_t* bl = &Bl[nt >> 1][(nt & 1) * 2];           \
                mma_bf16(acc[mt][nt], Ah[mt], bh);                         \
                mma_bf16(acc[mt][nt], Ah[mt], bl);                         \
                mma_bf16(acc[mt][nt], Al[mt], bh);                         \
            }                                                              \
    }

#define ACC_ZERO(acc)                                                     \
    _Pragma("unroll")                                                     \
    for (int mt = 0; mt < 4; mt++)                                        \
        _Pragma("unroll")                                                 \
        for (int nt = 0; nt < 4; nt++)                                    \
            _Pragma("unroll")                                             \
            for (int q = 0; q < 4; q++) acc[mt][nt][q] = 0.f;

// ===========================================================================
// Core all-bf16 GEMM, 2-stage cp.async pipeline (depth 1), 2 CTAs/SM.
// ===========================================================================
__device__ __forceinline__ void gemm_core(const __nv_bfloat16* Ah_, const __nv_bfloat16* Al_,
                                          const __nv_bfloat16* Bh_, const __nv_bfloat16* Bl_,
                                          const float* __restrict__ bias, float scale,
                                          float* outF, uint32_t* outH, uint32_t* outL,
                                          int mode, int m0, int n0)
{
    extern __shared__ uint32_t dsm[];
    MMA_IDX
    const uint32_t base = smem_u32(dsm);

    const char* gAh = (const char*)(Ah_ + (size_t)m0 * Dd);
    const char* gAl = (const char*)(Al_ + (size_t)m0 * Dd);
    const char* gBh = (const char*)(Bh_ + (size_t)n0 * Dd);
    const char* gBl = (const char*)(Bl_ + (size_t)n0 * Dd);
    const int WS = Dd * 2;

    float acc[4][4][4];
    ACC_ZERO(acc)

    // prologue: stage 0
    {
        CP_TILE(base + 0 * TILE_B, gAh, WS)
        CP_TILE(base + 1 * TILE_B, gAl, WS)
        CP_TILE(base + 2 * TILE_B, gBh, WS)
        CP_TILE(base + 3 * TILE_B, gBl, WS)
        cpa_commit();
    }

#pragma unroll 1
    for (int c = 0; c < 64; c++) {
        cpa_wait<0>();
        __syncthreads();               // stage c&1 visible; iter c-1 MMA done
        if (c + 1 < 64) {
            const uint32_t sb = base + ((c + 1) & 1) * 4 * TILE_B;
            CP_TILE(sb + 0 * TILE_B, gAh + (c + 1) * 64, WS)
            CP_TILE(sb + 1 * TILE_B, gAl + (c + 1) * 64, WS)
            CP_TILE(sb + 2 * TILE_B, gBh + (c + 1) * 64, WS)
            CP_TILE(sb + 3 * TILE_B, gBl + (c + 1) * 64, WS)
            cpa_commit();
        }
        const uint32_t pb = base + (c & 1) * 4 * TILE_B;
        MMA_CHUNK(acc, pb, pb + TILE_B, pb + 2 * TILE_B, pb + 3 * TILE_B)
    }

    const int g = l >> 2, tg = l & 3;
#pragma unroll
    for (int mt = 0; mt < 4; mt++) {
        const int r0 = m0 + m_off + mt * 16 + g;
#pragma unroll
        for (int nt = 0; nt < 4; nt++) {
            const int col = n0 + n_off + nt * 8 + tg * 2;
            const float b0v = bias[col], b1v = bias[col + 1];
            const float v00 = (acc[mt][nt][0] + b0v) * scale;
            const float v01 = (acc[mt][nt][1] + b1v) * scale;
            const float v10 = (acc[mt][nt][2] + b0v) * scale;
            const float v11 = (acc[mt][nt][3] + b1v) * scale;
            if (mode == 0) {
                *reinterpret_cast<float2*>(outF + (size_t)r0 * Dd + col) = make_float2(v00, v01);
                *reinterpret_cast<float2*>(outF + (size_t)(r0 + 8) * Dd + col) = make_float2(v10, v11);
            } else {
                uint32_t h, lo;
                split2(v00, v01, h, lo);
                outH[((size_t)r0 * Dd + col) >> 1] = h;
                outL[((size_t)r0 * Dd + col) >> 1] = lo;
                split2(v10, v11, h, lo);
                outH[((size_t)(r0 + 8) * Dd + col) >> 1] = h;
                outL[((size_t)(r0 + 8) * Dd + col) >> 1] = lo;
            }
        }
    }
}

__global__ __launch_bounds__(256, 2)
void mma_projqk_kernel(const float* __restrict__ bq, const float* __restrict__ bk)
{
    const int z = blockIdx.z;  // 0=Q, 1=K
    const __nv_bfloat16* Bh = g_wth + (size_t)z * Dd * Dd;
    const __nv_bfloat16* Bl = g_wtl + (size_t)z * Dd * Dd;
    const int m0 = blockIdx.y * 128, n0 = blockIdx.x * 128;
    if (z == 0)
        gemm_core(g_xh, g_xl, Bh, Bl, bq, QSCALE, nullptr,
                  (uint32_t*)g_qh, (uint32_t*)g_ql, 1, m0, n0);
    else
        gemm_core(g_xh, g_xl, Bh, Bl, bk, 1.0f, nullptr,
                  (uint32_t*)g_kh, (uint32_t*)g_kl, 1, m0, n0);
}

__global__ __launch_bounds__(256, 2)
void mma_projv_kernel(const float* __restrict__ bv)
{
    const __nv_bfloat16* Bh = g_wth + (size_t)2 * Dd * Dd;
    const __nv_bfloat16* Bl = g_wtl + (size_t)2 * Dd * Dd;
    gemm_core(g_xh, g_xl, Bh, Bl, bv, 1.0f, g_v, nullptr, nullptr, 0,
              blockIdx.y * 128, blockIdx.x * 128);
}

__global__ __launch_bounds__(256, 2)
void mma_oproj_kernel(const float* __restrict__ ob, float* __restrict__ out)
{
    gemm_core(g_ctxh, g_ctxl, g_woh, g_wol, ob, 1.0f, out, nullptr, nullptr, 0,
              blockIdx.y * 128, blockIdx.x * 128);
}

// ===========================================================================
// Logits: persistent split-Q, K streamed depth-1 double-buffer.
// No max subtraction: stores exp(logit), row sums -> g_l.
// ===========================================================================
__global__ __launch_bounds__(256, 2)
void mma_logits_kernel(const float* __restrict__ biasTS, float* __restrict__ probs)
{
    extern __shared__ uint32_t dsm[];
    __shared__ float red_s[128][4];

    const int bn = blockIdx.y;
    const int b = bn >> 4;
    const int n = bn & 15;
    const int t0 = blockIdx.x * 128;

    const char* gQh = (const char*)(g_qh + (size_t)(b * Tt + t0) * Dd + n * Hd);
    const char* gQl = (const char*)(g_ql + (size_t)(b * Tt + t0) * Dd + n * Hd);
    const char* gKh = (const char*)(g_kh + (size_t)b * Tt * Dd + n * Hd);
    const char* gKl = (const char*)(g_kl + (size_t)b * Tt * Dd + n * Hd);
    float* __restrict__ Lout = probs + (size_t)bn * Tt * Ss;
    const int WS = Dd * 2;

    MMA_IDX
    const uint32_t base = smem_u32(dsm);
    const int g = l >> 2, tg = l & 3;

    // Q persistent (tiles 0..7) + K chunk 0 (tiles 8,9); one group.
#pragma unroll
    for (int kc = 0; kc < 4; kc++) {
        CP_TILE(base + (2 * kc) * TILE_B, gQh + kc * 64, WS)
        CP_TILE(base + (2 * kc + 1) * TILE_B, gQl + kc * 64, WS)
    }
    CP_TILE(base + 8 * TILE_B, gKh, WS)
    CP_TILE(base + 9 * TILE_B, gKl, WS)
    cpa_commit();

    float srun[4][2];
#pragma unroll
    for (int mt = 0; mt < 4; mt++) { srun[mt][0] = 0.f; srun[mt][1] = 0.f; }

#pragma unroll 1
    for (int st = 0; st < 16; st++) {
        const int s0 = st * 128;
        float acc[4][4][4];
        ACC_ZERO(acc)

#pragma unroll 1
        for (int kc2 = 0; kc2 < 4; kc2++) {
            const int cc = st * 4 + kc2;
            cpa_wait<0>();
            __syncthreads();   // K buf cc&1 ready; MMA of cc-1 done
            if (cc + 1 < 64) { // prefetch next K chunk into the OTHER buffer
                const int nc = cc + 1;
                const size_t off = (size_t)(nc >> 2) * 128 * WS + (size_t)(nc & 3) * 64;
                const uint32_t sb = base + (8 + (nc & 1) * 2) * TILE_B;
                CP_TILE(sb, gKh + off, WS)
                CP_TILE(sb + TILE_B, gKl + off, WS)
                cpa_commit();
            }
            MMA_CHUNK(acc, base + (2 * kc2) * TILE_B, base + (2 * kc2 + 1) * TILE_B,
                      base + (8 + (cc & 1) * 2) * TILE_B, base + (9 + (cc & 1) * 2) * TILE_B)
        }

        // Epilogue: bias add, exp, store exp-values, accumulate row sums
#pragma unroll
        for (int mt = 0; mt < 4; mt++) {
            const int r1 = t0 + m_off + mt * 16 + g;
            const int r2 = r1 + 8;
            float s1 = 0.f, s2 = 0.f;
#pragma unroll
            for (int nt = 0; nt < 4; nt++) {
                const int col = s0 + n_off + nt * 8 + tg * 2;
                float2 c1 = *reinterpret_cast<const float2*>(biasTS + (size_t)r1 * Ss + col);
                float2 c2 = *reinterpret_cast<const float2*>(biasTS + (size_t)r2 * Ss + col);
                const float e10 = __expf(acc[mt][nt][0] + c1.x);
                const float e11 = __expf(acc[mt][nt][1] + c1.y);
                const float e20 = __expf(acc[mt][nt][2] + c2.x);
                const float e21 = __expf(acc[mt][nt][3] + c2.y);
                s1 += e10 + e11;
                s2 += e20 + e21;
                *reinterpret_cast<float2*>(Lout + (size_t)r1 * Ss + col) = make_float2(e10, e11);
                *reinterpret_cast<float2*>(Lout + (size_t)r2 * Ss + col) = make_float2(e20, e21);
            }
            srun[mt][0] += s1;
            srun[mt][1] += s2;
        }
    }

    // Reduce sums: over 4 lanes (tg) sharing each row, then across 4 n-warps.
#pragma unroll
    for (int mt = 0; mt < 4; mt++)
#pragma unroll
        for (int i = 0; i < 2; i++) {
            float s = srun[mt][i];
            s += __shfl_xor_sync(0xffffffffu, s, 1);
            s += __shfl_xor_sync(0xffffffffu, s, 2);
            if (tg == 0) {
                const int rl = m_off + mt * 16 + g + i * 8;
                red_s[rl][wid >> 1] = s;
            }
        }
    __syncthreads();
    if (tid < 128) {
        g_l[(size_t)bn * Tt + t0 + tid] =
            red_s[tid][0] + red_s[tid][1] + red_s[tid][2] + red_s[tid][3];
    }
}

// ===========================================================================
// Normalize (in-place: probs = exp * inv) + PV -> ctx split bf16.
// A double-buffered (2), B triple-buffered (3) -> ONE barrier per chunk.
// ===========================================================================
__global__ __launch_bounds__(256, 2)
void mma_pv_kernel(float* __restrict__ probs)
{
    extern __shared__ uint32_t dsm[];
    __shared__ float sm_inv[128];

    const int bn = blockIdx.y;
    const int b = bn >> 4;
    const int n = bn & 15;
    const int t0 = blockIdx.x * 128;

    float* __restrict__ Lp = probs + (size_t)bn * Tt * Ss;
    const char* gBh = (const char*)(g_vth + (size_t)bn * Hd * Tt);
    const char* gBl = (const char*)(g_vtl + (size_t)bn * Hd * Tt);
    const int WS = Tt * 2;

    MMA_IDX
    const uint32_t base = smem_u32(dsm);

    if (tid < 128)
        sm_inv[tid] = 1.0f / g_l[(size_t)bn * Tt + t0 + tid];
    __syncthreads();

    const float iv[4] = {sm_inv[lrow], sm_inv[lrow + 32], sm_inv[lrow + 64], sm_inv[lrow + 96]};

    float acc[4][4][4];
    ACC_ZERO(acc)

    // Prologue: A0 (register path), B0 and B1 (cp.async groups 0, 1)
    {
        float4 va[4];
#pragma unroll
        for (int j = 0; j < 4; j++) {
            const int row = lrow + j * 32;
            float4 pv = *reinterpret_cast<const float4*>(Lp + (size_t)(t0 + row) * Ss + kq);
            pv.x *= iv[j]; pv.y *= iv[j]; pv.z *= iv[j]; pv.w *= iv[j];
            *reinterpret_cast<float4*>(Lp + (size_t)(t0 + row) * Ss + kq) = pv;
            va[j] = pv;
        }
#pragma unroll
        for (int j = 0; j < 4; j++) SPLIT_STORE(dsm, dsm + TILE_U32, va[j], j)
        CP_TILE(base + 4 * TILE_B, gBh, WS)
        CP_TILE(base + 5 * TILE_B, gBl, WS)
        cpa_commit();
        CP_TILE(base + 6 * TILE_B, gBh + 64, WS)
        CP_TILE(base + 7 * TILE_B, gBl + 64, WS)
        cpa_commit();
    }

#pragma unroll 1
    for (int c = 0; c < 64; c++) {
        float4 va[4];
        if (c + 1 < 64) {
#pragma unroll
            for (int j = 0; j < 4; j++) {
                const int row = lrow + j * 32;
                va[j] = *reinterpret_cast<const float4*>(
                    Lp + (size_t)(t0 + row) * Ss + (c + 1) * 32 + kq);
            }
        }
        cpa_wait<1>();
        __syncthreads();
        if (c + 1 < 64) {
#pragma unroll
            for (int j = 0; j < 4; j++) {
                const int row = lrow + j * 32;
                va[j].x *= iv[j]; va[j].y *= iv[j];
                va[j].z *= iv[j]; va[j].w *= iv[j];
                *reinterpret_cast<float4*>(
                    Lp + (size_t)(t0 + row) * Ss + (c + 1) * 32 + kq) = va[j];
            }
            uint32_t* ah = dsm + ((c + 1) & 1) * 2 * TILE_U32;
#pragma unroll
            for (int j = 0; j < 4; j++) SPLIT_STORE(ah, ah + TILE_U32, va[j], j)
            if (c + 2 < 64) {
                const uint32_t sb = base + (4 + ((c + 2) % 3) * 2) * TILE_B;
                CP_TILE(sb, gBh + (c + 2) * 64, WS)
                CP_TILE(sb + TILE_B, gBl + (c + 2) * 64, WS)
            }
            cpa_commit();
        }
        const uint32_t ab = base + (c & 1) * 2 * TILE_B;
        const uint32_t bb = base + (4 + (c % 3) * 2) * TILE_B;
        MMA_CHUNK(acc, ab, ab + TILE_B, bb, bb + TILE_B)
    }

    const int g = l >> 2, tg = l & 3;
    uint32_t* ch = (uint32_t*)g_ctxh;
    uint32_t* cl = (uint32_t*)g_ctxl;
#pragma unroll
    for (int mt = 0; mt < 4; mt++) {
        const int r0 = t0 + m_off + mt * 16 + g;
#pragma unroll
        for (int nt = 0; nt < 4; nt++) {
            const int gcol = n * Hd + n_off + nt * 8 + tg * 2;
            uint32_t h, lo;
            split2(acc[mt][nt][0], acc[mt][nt][1], h, lo);
            ch[((size_t)(b * Tt + r0) * Dd + gcol) >> 1] = h;
            cl[((size_t)(b * Tt + r0) * Dd + gcol) >> 1] = lo;
            split2(acc[mt][nt][2], acc[mt][nt][3], h, lo);
            ch[((size_t)(b * Tt + r0 + 8) * Dd + gcol) >> 1] = h;
            cl[((size_t)(b * Tt + r0 + 8) * Dd + gcol) >> 1] = lo;
        }
    }
}

// ===========================================================================
// Prep kernels
// ===========================================================================
__global__ void split_kernel(const float4* __restrict__ src, uint32_t* __restrict__ dh,
                             uint32_t* __restrict__ dl, int n4)
{
    const int i = blockIdx.x * blockDim.x + threadIdx.x;
    if (i < n4) {
        float4 v = src[i];
        uint32_t h0, l0, h1, l1;
        split2(v.x, v.y, h0, l0);
        split2(v.z, v.w, h1, l1);
        dh[i * 2] = h0; dh[i * 2 + 1] = h1;
        dl[i * 2] = l0; dl[i * 2 + 1] = l1;
    }
}

// zbase lets us launch subsets of {Wq, Wk, Wv} on different streams.
__global__ void transpose_w_split_kernel(const float* __restrict__ Wq,
                                         const float* __restrict__ Wk,
                                         const float* __restrict__ Wv, int zbase)
{
    __shared__ float ts[32][33];
    const int z = zbase + blockIdx.z;
    const float* W = (z == 0) ? Wq : (z == 1) ? Wk : Wv;
    __nv_bfloat16* oh = g_wth + (size_t)z * Dd * Dd;
    __nv_bfloat16* ol = g_wtl + (size_t)z * Dd * Dd;
    const int bx = blockIdx.x * 32, by = blockIdx.y * 32;
    const int tx = threadIdx.x, ty = threadIdx.y;
#pragma unroll
    for (int r = 0; r < 32; r += 8)
        ts[ty + r][tx] = W[(size_t)(by + ty + r) * Dd + bx + tx];
    __syncthreads();
#pragma unroll
    for (int r = 0; r < 32; r += 8) {
        const float v = ts[tx][ty + r];
        const __nv_bfloat16 h = __float2bfloat16(v);
        const __nv_bfloat16 lo = __float2bfloat16(v - __bfloat162float(h));
        const size_t idx = (size_t)(bx + ty + r) * Dd + by + tx;
        oh[idx] = h;
        ol[idx] = lo;
    }
}

// g_vth/g_vtl[bn][h][s] = split(g_v[b][s][n*128+h])
__global__ void transpose_v_split_kernel()
{
    __shared__ float ts[32][33];
    const int bn = blockIdx.z;
    const int b = bn >> 4;
    const int n = bn & 15;
    const int s0 = blockIdx.x * 32, h0 = blockIdx.y * 32;
    const int tx = threadIdx.x, ty = threadIdx.y;
#pragma unroll
    for (int r = 0; r < 32; r += 8)
        ts[ty + r][tx] = g_v[(size_t)(b * Tt + s0 + ty + r) * Dd + n * Hd + h0 + tx];
    __syncthreads();
#pragma unroll
    for (int r = 0; r < 32; r += 8) {
        const float v = ts[tx][ty + r];
        const __nv_bfloat16 h = __float2bfloat16(v);
        const __nv_bfloat16 lo = __float2bfloat16(v - __bfloat162float(h));
        const size_t idx = ((size_t)bn * Hd + h0 + ty + r) * Tt + s0 + tx;
        g_vth[idx] = h;
        g_vtl[idx] = lo;
    }
}

// ===========================================================================
extern "C" void kernel_launch(void* const* d_in, const int* in_sizes, int n_in,
                              void* d_out, int out_size)
{
    const float* query  = (const float*)d_in[0];
    const float* biasTS = (const float*)d_in[1];
    const float* wq = (const float*)d_in[2];
    const float* bq = (const float*)d_in[3];
    const float* wk = (const float*)d_in[4];
    const float* bk = (const float*)d_in[5];
    const float* wv = (const float*)d_in[6];
    const float* bv = (const float*)d_in[7];
    const float* wo = (const float*)d_in[8];
    const float* obias = (const float*)d_in[9];

    float* data_out  = (float*)d_out;
    float* probs_out = data_out + (size_t)Bb * Tt * Dd;

    static bool init_done = false;
    static cudaStream_t s_aux = nullptr;
    static cudaEvent_t ev_fork = nullptr, ev_join = nullptr;
    if (!init_done) {
        cudaFuncSetAttribute(mma_projqk_kernel,
                             cudaFuncAttributeMaxDynamicSharedMemorySize, GEMM_SMEM);
        cudaFuncSetAttribute(mma_projv_kernel,
                             cudaFuncAttributeMaxDynamicSharedMemorySize, GEMM_SMEM);
        cudaFuncSetAttribute(mma_oproj_kernel,
                             cudaFuncAttributeMaxDynamicSharedMemorySize, GEMM_SMEM);
        cudaFuncSetAttribute(mma_logits_kernel,
                             cudaFuncAttributeMaxDynamicSharedMemorySize, LOGITS_SMEM);
        cudaFuncSetAttribute(mma_pv_kernel,
                             cudaFuncAttributeMaxDynamicSharedMemorySize, PV_SMEM);
        cudaStreamCreateWithFlags(&s_aux, cudaStreamNonBlocking);
        cudaEventCreateWithFlags(&ev_fork, cudaEventDisableTiming);
        cudaEventCreateWithFlags(&ev_join, cudaEventDisableTiming);
        init_done = true;
    }

    uint32_t *xh, *xl, *woh, *wol;
    cudaGetSymbolAddress((void**)&xh, g_xh);
    cudaGetSymbolAddress((void**)&xl, g_xl);
    cudaGetSymbolAddress((void**)&woh, g_woh);
    cudaGetSymbolAddress((void**)&wol, g_wol);

    // ---- main stream (0): split X (needed by both branches) ----
    split_kernel<<<(Bb * Tt * Dd / 4 + 255) / 256, 256>>>(
        (const float4*)query, xh, xl, Bb * Tt * Dd / 4);

    // ---- fork immediately after split_x: aux owns W_v transpose + V branch ----
    cudaEventRecord(ev_fork, 0);
    cudaStreamWaitEvent(s_aux, ev_fork, 0);
    transpose_w_split_kernel<<<dim3(Dd / 32, Dd / 32, 1), dim3(32, 8), 0, s_aux>>>(
        wq, wk, wv, 2);
    mma_projv_kernel<<<dim3(Dd / 128, (Bb * Tt) / 128), 256, GEMM_SMEM, s_aux>>>(bv);
    transpose_v_split_kernel<<<dim3(Tt / 32, Hd / 32, Bb * Nh), dim3(32, 8), 0, s_aux>>>();
    split_kernel<<<(Dd * Dd / 4 + 255) / 256, 256, 0, s_aux>>>(
        (const float4*)wo, woh, wol, Dd * Dd / 4);
    cudaEventRecord(ev_join, s_aux);

    // ---- main stream: W_q/W_k transpose -> Q,K proj -> logits ----
    transpose_w_split_kernel<<<dim3(Dd / 32, Dd / 32, 2), dim3(32, 8)>>>(wq, wk, wv, 0);
    mma_projqk_kernel<<<dim3(Dd / 128, (Bb * Tt) / 128, 2), 256, GEMM_SMEM>>>(bq, bk);
    mma_logits_kernel<<<dim3(Tt / 128, Bb * Nh), 256, LOGITS_SMEM>>>(biasTS, probs_out);

    // ---- join: pv needs Vt + logits; oproj needs ctx + Wo split ----
    cudaStreamWaitEvent(0, ev_join, 0);
    mma_pv_kernel<<<dim3(Tt / 128, Bb * Nh), 256, PV_SMEM>>>(probs_out);
    mma_oproj_kernel<<<dim3(Dd / 128, (Bb * Tt) / 128), 256, GEMM_SMEM>>>(obias, data_out);
}